// round 12
// baseline (speedup 1.0000x reference)
#include <cuda_runtime.h>

// SampleConditionalGMM: out = stds[b, lut[label], c] * noise + means[b, lut[label], c]
// Shapes: label_map [2,160,160,160,1] i32, means/stds [2,25,2] f32,
//         noise/out [2,160,160,160,2] f32.
//
// R10: conflict-free REP=8 float4 gather (R3/R9, measured best) + VPT=8 to
// double per-thread front-batched MLP (6 LDGs in flight before first use).
// Batch id via gridDim.y (no divide). 32-bit indexing, streaming hints.

#define NL 25          // number of generation labels
#define MAXL 48        // max label value + 1
#define REP 8          // replication factor (float4 columns per 128B row)
#define VOX 4096000    // 160*160*160 voxels per batch
#define VPT 8          // voxels per thread
#define VPB 2048       // voxels per block (256 threads * 8)
#define BLOCKS_PER_BATCH (VOX / VPB)   // 2000

__constant__ int c_gen_labels[NL] = {
    0, 2, 3, 4, 5, 7, 8, 10, 11, 12, 13, 14, 15, 16, 17, 18,
    24, 26, 28, 41, 42, 43, 44, 46, 47
};

__global__ __launch_bounds__(256)
void gmm_sample_kernel(const int*   __restrict__ label,
                       const float* __restrict__ means,
                       const float* __restrict__ stds,
                       const float* __restrict__ noise,
                       float*       __restrict__ out)
{
    __shared__ float4 s_tab[MAXL * REP];   // 6144 B

    const int t = threadIdx.x;
    const int b = blockIdx.y;              // batch id, no divide

    if (t < NL * REP) {
        const int li  = t >> 3;            // compacted label index 0..24
        const int col = t & 7;             // replica column
        const int lbl = c_gen_labels[li];
        const float2 m = *reinterpret_cast<const float2*>(means + (b * NL + li) * 2);
        const float2 s = *reinterpret_cast<const float2*>(stds  + (b * NL + li) * 2);
        s_tab[lbl * REP + col] = make_float4(s.x, s.y, m.x, m.y);
    }
    __syncthreads();

    // Offsets within one batch fit easily in 32 bits; add batch base as int32
    // too (max element index 2*VOX*2 = 32.8M).
    const int v = b * VOX + blockIdx.x * VPB + t * VPT;

    // Front-batch all 6 global loads (maximize MLP before first use).
    const int4* lp = reinterpret_cast<const int4*>(label + v);
    const int4 la = __ldcs(lp);
    const int4 lc = __ldcs(lp + 1);

    const float4* np = reinterpret_cast<const float4*>(noise + (size_t)v * 2);
    const float4 n0 = __ldcs(np);
    const float4 n1 = __ldcs(np + 1);
    const float4 n2 = __ldcs(np + 2);
    const float4 n3 = __ldcs(np + 3);

    const int col = t & 7;   // fixed conflict-free column for this lane

    const float4 t0 = s_tab[la.x * REP + col];
    const float4 t1 = s_tab[la.y * REP + col];
    const float4 t2 = s_tab[la.z * REP + col];
    const float4 t3 = s_tab[la.w * REP + col];
    const float4 t4 = s_tab[lc.x * REP + col];
    const float4 t5 = s_tab[lc.y * REP + col];
    const float4 t6 = s_tab[lc.z * REP + col];
    const float4 t7 = s_tab[lc.w * REP + col];

    float4 o0, o1, o2, o3;
    o0.x = fmaf(t0.x, n0.x, t0.z);  o0.y = fmaf(t0.y, n0.y, t0.w);
    o0.z = fmaf(t1.x, n0.z, t1.z);  o0.w = fmaf(t1.y, n0.w, t1.w);
    o1.x = fmaf(t2.x, n1.x, t2.z);  o1.y = fmaf(t2.y, n1.y, t2.w);
    o1.z = fmaf(t3.x, n1.z, t3.z);  o1.w = fmaf(t3.y, n1.w, t3.w);
    o2.x = fmaf(t4.x, n2.x, t4.z);  o2.y = fmaf(t4.y, n2.y, t4.w);
    o2.z = fmaf(t5.x, n2.z, t5.z);  o2.w = fmaf(t5.y, n2.w, t5.w);
    o3.x = fmaf(t6.x, n3.x, t6.z);  o3.y = fmaf(t6.y, n3.y, t6.w);
    o3.z = fmaf(t7.x, n3.z, t7.z);  o3.w = fmaf(t7.y, n3.w, t7.w);

    float4* op = reinterpret_cast<float4*>(out + (size_t)v * 2);
    __stcs(op,     o0);
    __stcs(op + 1, o1);
    __stcs(op + 2, o2);
    __stcs(op + 3, o3);
}

extern "C" void kernel_launch(void* const* d_in, const int* in_sizes, int n_in,
                              void* d_out, int out_size)
{
    const int*   label = (const int*)  d_in[0];  // [2,160,160,160,1]
    const float* means = (const float*)d_in[1];  // [2,25,2]
    const float* stds  = (const float*)d_in[2];  // [2,25,2]
    const float* noise = (const float*)d_in[3];  // [2,160,160,160,2]
    float*       out   = (float*)d_out;

    dim3 grid(BLOCKS_PER_BATCH, 2);              // 2000 x 2 batches
    gmm_sample_kernel<<<grid, 256>>>(label, means, stds, noise, out);
}

// round 13
// speedup vs baseline: 1.1606x; 1.1606x over previous
#include <cuda_runtime.h>

// SampleConditionalGMM: out = stds[b, lut[label], c] * noise + means[b, lut[label], c]
// Shapes: label_map [2,160,160,160,1] i32, means/stds [2,25,2] f32,
//         noise/out [2,160,160,160,2] f32.
//
// Per-thread shape is R9's measured best: VPT=4, conflict-free REP=8 float4
// gather (s_tab[lbl*8 + (tid&7)] -> every 8-lane LDS.128 phase hits 8 distinct
// columns), 32-bit indexing, streaming hints. R13 delta: 512-thread blocks
// (same per-warp behavior, half the block count / table fills / barriers).

#define NL 25          // number of generation labels
#define MAXL 48        // max label value + 1
#define REP 8          // replication factor (float4 columns per 128B row)
#define VOX 4096000    // 160*160*160 voxels per batch
#define VPT 4          // voxels per thread
#define TPB 512        // threads per block
#define VPB (TPB * VPT)                 // 2048 voxels per block
#define BLOCKS_PER_BATCH (VOX / VPB)    // 2000

__constant__ int c_gen_labels[NL] = {
    0, 2, 3, 4, 5, 7, 8, 10, 11, 12, 13, 14, 15, 16, 17, 18,
    24, 26, 28, 41, 42, 43, 44, 46, 47
};

__global__ __launch_bounds__(TPB)
void gmm_sample_kernel(const int*   __restrict__ label,
                       const float* __restrict__ means,
                       const float* __restrict__ stds,
                       const float* __restrict__ noise,
                       float*       __restrict__ out)
{
    __shared__ float4 s_tab[MAXL * REP];   // 6144 B

    const int t = threadIdx.x;
    const int b = blockIdx.y;              // batch id, no divide

    // Fill: 25 labels x 8 replicas = 200 float4, one STS.128 per thread.
    if (t < NL * REP) {
        const int li  = t >> 3;            // compacted label index 0..24
        const int col = t & 7;             // replica column
        const int lbl = c_gen_labels[li];
        const float2 m = *reinterpret_cast<const float2*>(means + (b * NL + li) * 2);
        const float2 s = *reinterpret_cast<const float2*>(stds  + (b * NL + li) * 2);
        s_tab[lbl * REP + col] = make_float4(s.x, s.y, m.x, m.y);
    }
    __syncthreads();

    // All offsets fit in 32 bits: max element index = 2*VOX*2 = 32.8M.
    const int v = b * VOX + blockIdx.x * VPB + t * VPT;

    const int4 lb = __ldcs(reinterpret_cast<const int4*>(label + v));

    const float4* np = reinterpret_cast<const float4*>(noise + (size_t)v * 2);
    const float4 n0 = __ldcs(np);
    const float4 n1 = __ldcs(np + 1);

    const int col = t & 7;   // fixed conflict-free column for this lane

    const float4 t0 = s_tab[lb.x * REP + col];
    const float4 t1 = s_tab[lb.y * REP + col];
    const float4 t2 = s_tab[lb.z * REP + col];
    const float4 t3 = s_tab[lb.w * REP + col];

    float4 o0, o1;
    o0.x = fmaf(t0.x, n0.x, t0.z);  o0.y = fmaf(t0.y, n0.y, t0.w);
    o0.z = fmaf(t1.x, n0.z, t1.z);  o0.w = fmaf(t1.y, n0.w, t1.w);
    o1.x = fmaf(t2.x, n1.x, t2.z);  o1.y = fmaf(t2.y, n1.y, t2.w);
    o1.z = fmaf(t3.x, n1.z, t3.z);  o1.w = fmaf(t3.y, n1.w, t3.w);

    float4* op = reinterpret_cast<float4*>(out + (size_t)v * 2);
    __stcs(op,     o0);
    __stcs(op + 1, o1);
}

extern "C" void kernel_launch(void* const* d_in, const int* in_sizes, int n_in,
                              void* d_out, int out_size)
{
    const int*   label = (const int*)  d_in[0];  // [2,160,160,160,1]
    const float* means = (const float*)d_in[1];  // [2,25,2]
    const float* stds  = (const float*)d_in[2];  // [2,25,2]
    const float* noise = (const float*)d_in[3];  // [2,160,160,160,2]
    float*       out   = (float*)d_out;

    dim3 grid(BLOCKS_PER_BATCH, 2);              // 2000 x 2 batches
    gmm_sample_kernel<<<grid, TPB>>>(label, means, stds, noise, out);
}